// round 9
// baseline (speedup 1.0000x reference)
#include <cuda_runtime.h>
#include <cuda_fp16.h>
#include <cstdint>

#define B_   4
#define N_   4096
#define DIN_ 128
#define H_   64
#define DO_  128
#define BM   64
#define BN   64
#define NTILES 64
#define NWRD 128
#define PACK_BLKS 2048
#define PROJ_ROWS 32
#define LOG2E 1.4426950408889634f

// smem layout (bytes). Q/K rows padded to 144B, V rows to 272B
#define OFF_QH  0
#define OFF_QL  9216
#define OFF_BUF 18432
#define BUFSZ   35840
#define KH_O    0
#define KL_O    9216
#define VH_O    18432
#define SMEM_ALLOC 90112

__device__ __half g_Qh[B_*N_*H_], g_Ql[B_*N_*H_];
__device__ __half g_Kh[B_*N_*H_], g_Kl[B_*N_*H_];
__device__ __half g_Vh[B_*N_*DO_];
__device__ unsigned g_adjb[N_*NWRD];

__device__ __forceinline__ uint32_t smem_u32(const void* p) {
    uint32_t a;
    asm("{ .reg .u64 t; cvta.to.shared.u64 t, %1; cvt.u32.u64 %0, t; }" : "=r"(a) : "l"(p));
    return a;
}
__device__ __forceinline__ void mma16816(float* c, const uint32_t* a, const uint32_t* b) {
    asm volatile("mma.sync.aligned.m16n8k16.row.col.f32.f16.f16.f32 "
        "{%0,%1,%2,%3}, {%4,%5,%6,%7}, {%8,%9}, {%0,%1,%2,%3};"
        : "+f"(c[0]), "+f"(c[1]), "+f"(c[2]), "+f"(c[3])
        : "r"(a[0]), "r"(a[1]), "r"(a[2]), "r"(a[3]), "r"(b[0]), "r"(b[1]));
}
__device__ __forceinline__ void ldsm_x4(uint32_t* r, uint32_t a) {
    asm volatile("ldmatrix.sync.aligned.m8n8.x4.shared.b16 {%0,%1,%2,%3}, [%4];"
        : "=r"(r[0]), "=r"(r[1]), "=r"(r[2]), "=r"(r[3]) : "r"(a));
}
__device__ __forceinline__ void ldsm_x4_t(uint32_t* r, uint32_t a) {
    asm volatile("ldmatrix.sync.aligned.m8n8.x4.trans.shared.b16 {%0,%1,%2,%3}, [%4];"
        : "=r"(r[0]), "=r"(r[1]), "=r"(r[2]), "=r"(r[3]) : "r"(a));
}
__device__ __forceinline__ void ldsm_x2_t(uint32_t* r, uint32_t a) {
    asm volatile("ldmatrix.sync.aligned.m8n8.x2.trans.shared.b16 {%0,%1}, [%2];"
        : "=r"(r[0]), "=r"(r[1]) : "r"(a));
}
__device__ __forceinline__ void cpa16(uint32_t dst, const void* src) {
    asm volatile("cp.async.cg.shared.global [%0], [%1], 16;" :: "r"(dst), "l"(src));
}
#define CP_COMMIT() asm volatile("cp.async.commit_group;" ::: "memory")
#define CP_WAIT(n)  asm volatile("cp.async.wait_group %0;" :: "n"(n) : "memory")

__device__ __forceinline__ uint32_t cvt_h2(float hi, float lo) {
    uint32_t r;
    asm("cvt.rn.f16x2.f32 %0, %1, %2;" : "=r"(r) : "f"(hi), "f"(lo));
    return r;
}
__device__ __forceinline__ uint32_t ex2_h2(uint32_t x) {
    uint32_t r;
    asm("ex2.approx.f16x2 %0, %1;" : "=r"(r) : "r"(x));
    return r;
}
__device__ __forceinline__ uint32_t hmax2u(uint32_t a, uint32_t b) {
    __half2 r = __hmax2(*(__half2*)&a, *(__half2*)&b);
    return *(uint32_t*)&r;
}

// ============== fused prep: adj bit-pack (MLP=8) + projections ==============
__global__ __launch_bounds__(256) void prep_kernel(
    const float* __restrict__ h, const int* __restrict__ adj,
    const float* __restrict__ Ws, const float* __restrict__ Wt,
    const float* __restrict__ Wc) {
    __shared__ float sh[PROJ_ROWS][DIN_];
    const int tid = threadIdx.x;

    if (blockIdx.x < PACK_BLKS) {
        int w = blockIdx.x * 256 + tid;
        const int4* p = (const int4*)(adj + (size_t)w * 32);
        unsigned word = 0;
        #pragma unroll
        for (int j = 0; j < 8; ++j) {
            int4 v = p[j];
            unsigned nib = (unsigned)(v.x > 0) | ((unsigned)(v.y > 0) << 1) |
                           ((unsigned)(v.z > 0) << 2) | ((unsigned)(v.w > 0) << 3);
            word |= nib << (j * 4);
        }
        g_adjb[w] = word;
        return;
    }

    const int row0 = (blockIdx.x - PACK_BLKS) * PROJ_ROWS;
    {
        const float4* src = (const float4*)(h + (size_t)row0 * DIN_);
        float4* dst = (float4*)&sh[0][0];
        for (int i = tid; i < PROJ_ROWS * DIN_ / 4; i += 256) dst[i] = src[i];
    }
    __syncthreads();

    const int c = tid;
    const float* W; int col, stride;
    if (c < 64)       { W = Ws; col = c;       stride = H_;  }
    else if (c < 128) { W = Wt; col = c - 64;  stride = H_;  }
    else              { W = Wc; col = c - 128; stride = DO_; }

    float a[PROJ_ROWS];
    #pragma unroll
    for (int r = 0; r < PROJ_ROWS; ++r) a[r] = 0.f;
    const float* wp = W + col;
    for (int k4 = 0; k4 < DIN_ / 4; ++k4) {
        float w0 = wp[(k4*4+0)*stride], w1 = wp[(k4*4+1)*stride];
        float w2 = wp[(k4*4+2)*stride], w3 = wp[(k4*4+3)*stride];
        #pragma unroll
        for (int r = 0; r < PROJ_ROWS; ++r) {
            float4 hv = *(const float4*)&sh[r][k4*4];
            a[r] = fmaf(hv.x, w0, fmaf(hv.y, w1, fmaf(hv.z, w2, fmaf(hv.w, w3, a[r]))));
        }
    }
    #pragma unroll
    for (int r = 0; r < PROJ_ROWS; ++r) {
        int rn = row0 + r;
        if (c < 64) {
            float q = a[r] * LOG2E;
            __half hi = __float2half_rn(q);
            __half lo = __float2half_rn(q - __half2float(hi));
            g_Qh[(size_t)rn*H_ + col] = hi; g_Ql[(size_t)rn*H_ + col] = lo;
        } else if (c < 128) {
            __half hi = __float2half_rn(a[r]);
            __half lo = __float2half_rn(a[r] - __half2float(hi));
            g_Kh[(size_t)rn*H_ + col] = hi; g_Kl[(size_t)rn*H_ + col] = lo;
        } else {
            g_Vh[(size_t)rn*DO_ + col] = __float2half_rn(a[r]);
        }
    }
}

// ============================ attention ============================
__device__ __forceinline__ void load_tile_async(
    uint32_t bufb, int tid, const __half* Kh, const __half* Kl, const __half* Vh) {
    #pragma unroll
    for (int i = tid; i < 512; i += 128) {
        int rr = i >> 3, x = i & 7;
        cpa16(bufb + KH_O + rr*144 + x*16, Kh + rr*H_ + x*8);
        cpa16(bufb + KL_O + rr*144 + x*16, Kl + rr*H_ + x*8);
    }
    #pragma unroll
    for (int i = tid; i < 1024; i += 128) {
        int rr = i >> 4, x = i & 15;
        cpa16(bufb + VH_O + rr*272 + x*16, Vh + rr*DO_ + x*8);
    }
    if (tid < 64) {
        asm volatile("st.shared.v4.b32 [%0], {%1,%2,%3,%4};"
            :: "r"(bufb + VH_O + tid*272 + 256),
               "r"(0x3C00u), "r"(0u), "r"(0u), "r"(0u) : "memory");
    }
}

__global__ __launch_bounds__(128, 2) void attn_kernel(float* __restrict__ out) {
    extern __shared__ char sm[];
    const uint32_t sbase = smem_u32(sm);
    const int tid = threadIdx.x, wm = tid >> 5, lane = tid & 31;
    const int bi = blockIdx.y, row0 = blockIdx.x * BM;

    const __half* Khb = g_Kh + (size_t)bi * N_ * H_;
    const __half* Klb = g_Kl + (size_t)bi * N_ * H_;
    const __half* Vhb = g_Vh + (size_t)bi * N_ * DO_;

    {
        const __half* Qh = g_Qh + ((size_t)bi * N_ + row0) * H_;
        const __half* Ql = g_Ql + ((size_t)bi * N_ + row0) * H_;
        #pragma unroll
        for (int i = tid; i < BM * 8; i += 128) {
            int rr = i >> 3, x = i & 7;
            *(uint4*)(sm + OFF_QH + rr*144 + x*16) = *(const uint4*)(Qh + rr*H_ + x*8);
            *(uint4*)(sm + OFF_QL + rr*144 + x*16) = *(const uint4*)(Ql + rr*H_ + x*8);
        }
    }
    load_tile_async(sbase + OFF_BUF, tid, Khb, Klb, Vhb);
    CP_COMMIT();
    __syncthreads();

    uint32_t qh[4][4], ql[4][4];
    {
        int qrow = wm * 16 + (lane & 15);
        uint32_t base = sbase + qrow * 144 + ((lane >> 4) & 1) * 16;
        #pragma unroll
        for (int ks = 0; ks < 4; ++ks) {
            ldsm_x4(qh[ks], base + OFF_QH + ks * 32);
            ldsm_x4(ql[ks], base + OFF_QL + ks * 32);
        }
    }

    float o[17][4];
    #pragma unroll
    for (int d = 0; d < 17; ++d) { o[d][0]=0.f; o[d][1]=0.f; o[d][2]=0.f; o[d][3]=0.f; }
    float m0 = -1e30f, m1 = -1e30f;

    const int r0 = lane >> 2;
    const int sh2 = (lane & 3) * 2;
    const unsigned* adjr0 = g_adjb + (size_t)(row0 + wm*16 + r0) * NWRD;
    const unsigned* adjr1 = adjr0 + 8 * NWRD;

    for (int jb = 0; jb < NTILES; ++jb) {
        const uint32_t buf = sbase + OFF_BUF + (jb & 1) * BUFSZ;
        if (jb + 1 < NTILES) {
            int c1 = (jb + 1) * BN;
            load_tile_async(sbase + OFF_BUF + ((jb+1)&1)*BUFSZ, tid,
                            Khb + (size_t)c1*H_, Klb + (size_t)c1*H_, Vhb + (size_t)c1*DO_);
            CP_COMMIT();
            CP_WAIT(1);
        } else {
            CP_WAIT(0);
        }
        __syncthreads();

        // hoist adjacency LDGs (L2 latency hides under the S-MMA block)
        unsigned aw0r = adjr0[jb*2], aw1r = adjr0[jb*2+1];
        unsigned aw2r = adjr1[jb*2], aw3r = adjr1[jb*2+1];

        // ---- S = Q K^T: batch LDSM, then 8-wide MMA sweeps (RAW dist 8) ----
        float s[8][4];
        #pragma unroll
        for (int nt = 0; nt < 8; ++nt) { s[nt][0]=0.f; s[nt][1]=0.f; s[nt][2]=0.f; s[nt][3]=0.f; }
        #pragma unroll
        for (int ks = 0; ks < 4; ++ks) {
            uint32_t kb[8][4];
            #pragma unroll
            for (int nt = 0; nt < 8; ++nt) {
                uint32_t ka = buf + ((lane & 16) ? KL_O : KH_O)
                            + (nt*8 + (lane&7))*144 + ks*32 + ((lane>>3)&1)*16;
                ldsm_x4(kb[nt], ka);
            }
            #pragma unroll
            for (int nt = 0; nt < 8; ++nt) mma16816(s[nt], qh[ks], kb[nt]);
            #pragma unroll
            for (int nt = 0; nt < 8; ++nt) mma16816(s[nt], qh[ks], kb[nt] + 2);
            #pragma unroll
            for (int nt = 0; nt < 8; ++nt) mma16816(s[nt], ql[ks], kb[nt]);
        }

        // ---- per-thread AND-masks ----
        unsigned x00 = aw0r >> sh2, x01 = aw1r >> sh2;
        unsigned x10 = aw2r >> sh2, x11 = aw3r >> sh2;
        uint32_t am0[8], am1[8];
        #pragma unroll
        for (int nt = 0; nt < 8; ++nt) {
            unsigned b0 = ((nt < 4 ? x00 : x01) >> (8*(nt&3))) & 3u;
            unsigned b1 = ((nt < 4 ? x10 : x11) >> (8*(nt&3))) & 3u;
            am0[nt] = ((b0 & 1u) ? 0xFFFFu : 0u) | ((b0 & 2u) ? 0xFFFF0000u : 0u);
            am1[nt] = ((b1 & 1u) ? 0xFFFFu : 0u) | ((b1 & 2u) ? 0xFFFF0000u : 0u);
        }

        // ---- masked row max via HMAX2 ----
        uint32_t hm0 = 0u, hm1 = 0u;
        #pragma unroll
        for (int nt = 0; nt < 8; ++nt) {
            hm0 = hmax2u(hm0, cvt_h2(s[nt][1], s[nt][0]) & am0[nt]);
            hm1 = hmax2u(hm1, cvt_h2(s[nt][3], s[nt][2]) & am1[nt]);
        }
        float lm0 = fmaxf(__low2float(*(__half2*)&hm0), __high2float(*(__half2*)&hm0));
        float lm1 = fmaxf(__low2float(*(__half2*)&hm1), __high2float(*(__half2*)&hm1));
        lm0 = fmaxf(lm0, __shfl_xor_sync(0xffffffffu, lm0, 1));
        lm0 = fmaxf(lm0, __shfl_xor_sync(0xffffffffu, lm0, 2));
        lm1 = fmaxf(lm1, __shfl_xor_sync(0xffffffffu, lm1, 1));
        lm1 = fmaxf(lm1, __shfl_xor_sync(0xffffffffu, lm1, 2));
        float mn0 = fmaxf(m0, lm0), mn1 = fmaxf(m1, lm1);
        float sc0 = exp2f(m0 - mn0), sc1 = exp2f(m1 - mn1);
        m0 = mn0; m1 = mn1;
        if (sc0 != 1.f || sc1 != 1.f) {
            #pragma unroll
            for (int d = 0; d < 17; ++d) {
                o[d][0] *= sc0; o[d][1] *= sc0; o[d][2] *= sc1; o[d][3] *= sc1;
            }
        }

        // ---- P = ex2(S - m) & mask ----
        uint32_t ph[4][4];
        #pragma unroll
        for (int nt = 0; nt < 8; ++nt) {
            float d0 = s[nt][0] - mn0, d1 = s[nt][1] - mn0;
            float d2 = s[nt][2] - mn1, d3 = s[nt][3] - mn1;
            ph[nt>>1][(nt&1)*2 + 0] = ex2_h2(cvt_h2(d1, d0)) & am0[nt];
            ph[nt>>1][(nt&1)*2 + 1] = ex2_h2(cvt_h2(d3, d2)) & am1[nt];
        }

        // ---- O += P V: dt-groups of 8, kk inner (16-way chain spacing) ----
        #pragma unroll
        for (int g = 0; g < 2; ++g) {
            #pragma unroll
            for (int kk = 0; kk < 4; ++kk) {
                uint32_t vv[16];
                uint32_t vb = buf + VH_O + (kk*16 + (lane&15))*272 + ((lane>>4)&1)*16;
                #pragma unroll
                for (int q = 0; q < 4; ++q)
                    ldsm_x4_t(vv + q*4, vb + (g*8 + q*2)*16);
                #pragma unroll
                for (int d = 0; d < 8; ++d)
                    mma16816(o[g*8 + d], ph[kk], vv + d*2);
            }
        }
        #pragma unroll
        for (int kk = 0; kk < 4; ++kk) {
            uint32_t va = buf + VH_O + (kk*16 + (lane&15))*272 + 256;
            uint32_t vv[2];
            ldsm_x2_t(vv, va);
            mma16816(o[16], ph[kk], vv);
        }
        __syncthreads();
    }

    // ---- epilogue ----
    float l0 = __shfl_sync(0xffffffffu, o[16][0], lane & ~3);
    float l1 = __shfl_sync(0xffffffffu, o[16][2], lane & ~3);
    float inv0 = 1.0f / l0, inv1 = 1.0f / l1;
    int gr0 = row0 + wm * 16 + r0;
    float* ob = out + ((size_t)bi * N_ + gr0) * DO_ + sh2;
    #pragma unroll
    for (int dt = 0; dt < 16; ++dt) {
        float2 v0 = make_float2(o[dt][0] * inv0, o[dt][1] * inv0);
        float2 v1 = make_float2(o[dt][2] * inv1, o[dt][3] * inv1);
        *(float2*)(ob + dt * 8)            = v0;
        *(float2*)(ob + 8 * DO_ + dt * 8)  = v1;
    }
}

// ---------------------------------------------------------------------------
extern "C" void kernel_launch(void* const* d_in, const int* in_sizes, int n_in,
                              void* d_out, int out_size) {
    const float* h   = (const float*)d_in[0];
    const int*   adj = (const int*)  d_in[1];
    const float* Ws  = (const float*)d_in[2];
    const float* Wt  = (const float*)d_in[3];
    const float* Wc  = (const float*)d_in[4];
    float* out = (float*)d_out;

    prep_kernel<<<PACK_BLKS + B_ * N_ / PROJ_ROWS, 256>>>(h, adj, Ws, Wt, Wc);

    cudaFuncSetAttribute(attn_kernel,
                         cudaFuncAttributeMaxDynamicSharedMemorySize, SMEM_ALLOC);
    dim3 grid(N_ / BM, B_);
    attn_kernel<<<grid, 128, SMEM_ALLOC>>>(out);
}